// round 16
// baseline (speedup 1.0000x reference)
#include <cuda_runtime.h>
#include <cuda_fp16.h>
#include <cstdint>
#include <cstddef>

// Problem constants (B=8, S=2048, D=1024, F=4096, E=8, capacity_factor=1.0)
#define T_TOK   16384
#define D_DIM   1024
#define F_DIM   4096
#define E_NUM   8
#define CAP     2048
#define CHUNK   256
#define NCHUNK  (T_TOK / CHUNK)

#define BM 128
#define BN 128
#define NTHREADS 128
#define ROWB 64              // 32 fp16 per k-tile row
#define STAGE_B 16384        // A 8KB + B 8KB per stage (3 stages = 48KB)

// ---------------- device scratch (~288 MB, proven-safe) ----------------
__device__ int   g_eidx[T_TOK];
__device__ float g_gate[T_TOK];
__device__ int   g_counts[NCHUNK][E_NUM];     // zero-init; GEMM1 re-zeroes after assign reads
__device__ int   g_tok_of_slot[E_NUM * CAP];
__device__ float g_slot_gate[E_NUM * CAP];

__device__ __half g_x16[(size_t)T_TOK * D_DIM];               //  32 MB
__device__ __half g_wt[(size_t)E_NUM * F_DIM * D_DIM];        //  64 MB  W1t
__device__ __half g_wt2[(size_t)E_NUM * D_DIM * F_DIM];       //  64 MB  W2t
__device__ __half g_h16[(size_t)E_NUM * CAP * F_DIM];         // 128 MB  H
__device__ uint4  g_zrow[512];                                //   8 KB zero row

// ---------------- PTX helpers ----------------
__device__ __forceinline__ uint32_t smem_u32(const void* p) {
    uint32_t a;
    asm("{ .reg .u64 t; cvta.to.shared.u64 t, %1; cvt.u32.u64 %0, t; }" : "=r"(a) : "l"(p));
    return a;
}
__device__ __forceinline__ void sts128(uint32_t a, uint4 v) {
    asm volatile("st.shared.v4.b32 [%0], {%1,%2,%3,%4};"
                 :: "r"(a), "r"(v.x), "r"(v.y), "r"(v.z), "r"(v.w) : "memory");
}
__device__ __forceinline__ void ldsm4(uint32_t& r0, uint32_t& r1, uint32_t& r2, uint32_t& r3, uint32_t a) {
    asm volatile("ldmatrix.sync.aligned.m8n8.x4.shared.b16 {%0,%1,%2,%3}, [%4];"
                 : "=r"(r0), "=r"(r1), "=r"(r2), "=r"(r3) : "r"(a));
}
__device__ __forceinline__ void mma16816(float* c, const uint32_t* a, const uint32_t* b) {
    asm volatile("mma.sync.aligned.m16n8k16.row.col.f32.f16.f16.f32 "
                 "{%0,%1,%2,%3}, {%4,%5,%6,%7}, {%8,%9}, {%0,%1,%2,%3};"
                 : "+f"(c[0]), "+f"(c[1]), "+f"(c[2]), "+f"(c[3])
                 : "r"(a[0]), "r"(a[1]), "r"(a[2]), "r"(a[3]), "r"(b[0]), "r"(b[1]));
}

// ---------------- 64x64 transpose+convert body (uses caller smem) ----------
// src [e][K][N] f32 (N contiguous) -> dst [e][N][K] fp16
__device__ __forceinline__ void convert_w_tile64(const float* __restrict__ W,
                                                 __half* __restrict__ dstbuf,
                                                 float* sbuf,   // >= 64*65 floats
                                                 int K, int N, int e, int k0, int n0,
                                                 int tid) {
    const float* src = W + (size_t)e * K * N;
    __half* d = dstbuf + (size_t)e * N * K;
    const int tx = tid & 15, ty = tid >> 4;        // (16, 16)
#pragma unroll
    for (int i = 0; i < 4; i++) {
        int kl = ty + i * 16;
        float4 v = *(const float4*)(src + (size_t)(k0 + kl) * N + n0 + tx * 4);
        float* row = sbuf + kl * 65;
        row[tx * 4 + 0] = v.x;
        row[tx * 4 + 1] = v.y;
        row[tx * 4 + 2] = v.z;
        row[tx * 4 + 3] = v.w;
    }
    __syncthreads();
#pragma unroll
    for (int i = 0; i < 4; i++) {
        int nl = ty + i * 16;
        __half h[4];
#pragma unroll
        for (int j = 0; j < 4; j++)
            h[j] = __float2half_rn(sbuf[(tx * 4 + j) * 65 + nl]);
        *(uint2*)(d + (size_t)(n0 + nl) * K + k0 + tx * 4) = *(uint2*)h;
    }
}

// ------ mega setup: router | reset | convert W1 | convert W2 (ONE launch) --
// b in [0,2048): router (+x16 conversion +chunk histogram) — dispatched first
// b in [2048,2112): reset slot tables / zero row
// b in [2112,2112+8192): W1 tiles;  b >= 2112+8192: W2 tiles
__global__ void mega_setup_kernel(const float* __restrict__ x,
                                  const float* __restrict__ Wr,
                                  const float* __restrict__ W1,
                                  const float* __restrict__ W2) {
    __shared__ float sh[8192];                    // 32 KB shared: Wr cache / transpose tile
    const int b = blockIdx.x;
    const int tid = threadIdx.x;

    if (b < 2048) {
        // ---- router: 8 warps, one token per warp
        for (int i = tid; i < D_DIM * E_NUM; i += blockDim.x)
            sh[i] = Wr[i];
        __syncthreads();

        const int warp = tid >> 5;
        const int lane = tid & 31;
        const int tok  = b * 8 + warp;
        const float* xr = x + (size_t)tok * D_DIM;
        __half* xo = g_x16 + (size_t)tok * D_DIM;

        float acc[E_NUM];
#pragma unroll
        for (int e = 0; e < E_NUM; e++) acc[e] = 0.f;
        for (int d = lane; d < D_DIM; d += 32) {
            float xv = xr[d];
            xo[d] = __float2half_rn(xv);
            const float* w = &sh[d * E_NUM];
#pragma unroll
            for (int e = 0; e < E_NUM; e++) acc[e] += xv * w[e];
        }
#pragma unroll
        for (int e = 0; e < E_NUM; e++) {
#pragma unroll
            for (int o = 16; o > 0; o >>= 1)
                acc[e] += __shfl_xor_sync(0xffffffffu, acc[e], o);
        }
        if (lane == 0) {
            int best = 0; float bm = acc[0];
#pragma unroll
            for (int e = 1; e < E_NUM; e++)
                if (acc[e] > bm) { bm = acc[e]; best = e; }
            float s = 0.f;
#pragma unroll
            for (int e = 0; e < E_NUM; e++) s += __expf(acc[e] - bm);
            g_eidx[tok] = best;
            g_gate[tok] = 1.0f / s;
            atomicAdd(&g_counts[tok >> 8][best], 1);
        }
    } else if (b < 2112) {
        int i = (b - 2048) * 256 + tid;
        g_tok_of_slot[i] = -1;
        g_slot_gate[i]   = 0.f;
        if (i < 512) g_zrow[i] = make_uint4(0u, 0u, 0u, 0u);
    } else if (b < 2112 + 8192) {
        int idx = b - 2112;
        int kt = idx & 15;             // 1024/64 = 16
        int nt = (idx >> 4) & 63;      // 4096/64 = 64
        int e  = idx >> 10;
        convert_w_tile64(W1, g_wt, sh, D_DIM, F_DIM, e, kt * 64, nt * 64, tid);
    } else {
        int idx = b - (2112 + 8192);
        int kt = idx & 63;             // 4096/64 = 64
        int nt = (idx >> 6) & 15;      // 1024/64 = 16
        int e  = idx >> 10;
        convert_w_tile64(W2, g_wt2, sh, F_DIM, D_DIM, e, kt * 64, nt * 64, tid);
    }
}

// ---------------- assign (in-place prefix base + zero output) --------------
// blocks [0,64): slot assignment for chunk b (computes its own per-expert base
//                by reducing g_counts over chunks < b — replaces the scan launch)
// blocks >= 64: zero the output tensor
__global__ void assign_kernel(float* __restrict__ out) {
    if (blockIdx.x >= 64) {
        size_t off = (size_t)(blockIdx.x - 64) * 256 + threadIdx.x;
        float4 z = make_float4(0.f, 0.f, 0.f, 0.f);
        float4* o = (float4*)out;
#pragma unroll
        for (int j = 0; j < 8; j++)
            o[off + (size_t)j * 524288] = z;
        return;
    }
    __shared__ int se[CHUNK];
    __shared__ int sbase[E_NUM];
    const int c = blockIdx.x;
    const int tid = threadIdx.x;
    const int w = tid >> 5, lane = tid & 31;

    // warp w computes base[w] = sum over chunks j < c of counts[j][w]
    {
        int v = 0;
        if (lane < c)      v  = g_counts[lane][w];
        if (lane + 32 < c) v += g_counts[lane + 32][w];
#pragma unroll
        for (int o = 16; o > 0; o >>= 1)
            v += __shfl_xor_sync(0xffffffffu, v, o);
        if (lane == 0) sbase[w] = v;
    }

    int tok = c * CHUNK + tid;
    int e = g_eidx[tok];
    se[tid] = e;
    __syncthreads();
    int local = 0;
    for (int j = 0; j < tid; j++) local += (se[j] == e);
    int rank = sbase[e] + local;
    if (rank < CAP) {
        int slot = e * CAP + rank;
        g_tok_of_slot[slot] = tok;
        g_slot_gate[slot]   = g_gate[tok];
    }
}

// ---------------- HMMA GEMM (frozen round-11 core) -------------------------
// smem swizzle: 16B granule g of row r stored at granule (g ^ ((r>>1)&3))
// PHASE 1: H = relu( gather(x16) @ W1t^T )  (K=1024); block (0,0,0) also
//          re-zeroes g_counts for the next graph replay (after assign read them)
// PHASE 2: out[tok] = gate * ( H @ W2t^T )  (K=4096)
template <int PHASE>
__global__ void __launch_bounds__(NTHREADS, 2)
moe_mma_gemm(float* __restrict__ out) {
    constexpr int KA = (PHASE == 1) ? D_DIM : F_DIM;
    constexpr int NC = KA / 32;
    constexpr int NT = (PHASE == 1) ? F_DIM : D_DIM;

    __shared__ uint4 dsm[3072];                 // 48 KB: 3 stages x (A 8KB + B 8KB)
    const uint32_t sbase = smem_u32(dsm);

    const int tid = threadIdx.x;
    const int e = blockIdx.z, m0 = blockIdx.y * BM, n0 = blockIdx.x * BN;

    if (PHASE == 1 && blockIdx.x == 0 && blockIdx.y == 0 && blockIdx.z == 0) {
        // re-zero chunk histogram for next replay (stream-ordered after assign)
        int* cnt = &g_counts[0][0];
#pragma unroll
        for (int j = 0; j < 4; j++)
            cnt[tid + j * 128] = 0;
    }

    // ---- load mapping
    const int rbase = tid >> 2;
    const int cix   = tid & 3;
    const uint32_t dst0 = (uint32_t)rbase * ROWB + (uint32_t)((cix ^ ((rbase >> 1) & 3)) << 4);

    const char* pA[4];
    const char* pB[4];
    uint32_t    mskA = 0;
#pragma unroll
    for (int i = 0; i < 4; i++) {
        int row = rbase + i * 32;
        if (PHASE == 1) {
            int tok = g_tok_of_slot[e * CAP + m0 + row];
            if (tok >= 0) { pA[i] = (const char*)(g_x16 + (size_t)tok * D_DIM) + cix * 16; mskA |= (1u << i); }
            else          { pA[i] = (const char*)g_zrow; }
        } else {
            pA[i] = (const char*)(g_h16 + (size_t)(e * CAP + m0 + row) * F_DIM) + cix * 16;
            mskA |= (1u << i);
        }
        const __half* wb = (PHASE == 1) ? g_wt : g_wt2;
        pB[i] = (const char*)(wb + ((size_t)e * NT + n0 + row) * KA) + cix * 16;
    }

    uint4 rA[4], rB[4];
    auto ldg_tile = [&](int c) {
        uint32_t koff = (uint32_t)c * ROWB;
#pragma unroll
        for (int i = 0; i < 4; i++) {
            rA[i] = *(const uint4*)(pA[i] + (((mskA >> i) & 1) ? koff : 0u));
            rB[i] = *(const uint4*)(pB[i] + koff);
        }
    };
    auto sts_tile = [&](int buf) {
        uint32_t aS = sbase + (uint32_t)buf * STAGE_B;
        uint32_t bS = aS + 8192;
#pragma unroll
        for (int i = 0; i < 4; i++) {
            sts128(aS + dst0 + i * 2048, rA[i]);
            sts128(bS + dst0 + i * 2048, rB[i]);
        }
    };

    // ---- compute mapping: 4 warps 2x2, warp tile 64x64
    const int w = tid >> 5, l = tid & 31;
    const int warp_m = (w & 1) * 64, warp_n = (w >> 1) * 64;
    const int a_ml = warp_m + (l & 15);
    const int a_ks = (l >> 4);
    const int b_nl = warp_n + (l & 7) + ((l & 16) >> 1);
    const int b_ks = (l >> 3) & 1;
    const int fa = (a_ml >> 1) & 3, fb = (b_nl >> 1) & 3;

    float acc[4][8][4];
#pragma unroll
    for (int i = 0; i < 4; i++)
#pragma unroll
        for (int j = 0; j < 8; j++)
#pragma unroll
            for (int q = 0; q < 4; q++) acc[i][j][q] = 0.f;

    ldg_tile(0);
    sts_tile(0);
    ldg_tile(1);

    int bufc = 0, bufs = 1;
#pragma unroll 2
    for (int c = 0; c < NC; c++) {
        if (c + 1 < NC) sts_tile(bufs);
        if (c + 2 < NC) ldg_tile(c + 2);
        __syncthreads();

        uint32_t aS = sbase + (uint32_t)bufc * STAGE_B;
        uint32_t bS = aS + 8192;
#pragma unroll
        for (int ks = 0; ks < 2; ks++) {
            uint32_t af[4][4], bf[4][4];
#pragma unroll
            for (int mf = 0; mf < 4; mf++) {
                uint32_t addr = aS + (uint32_t)(a_ml + mf * 16) * ROWB
                              + (uint32_t)(((ks * 2 + a_ks) ^ fa) << 4);
                ldsm4(af[mf][0], af[mf][1], af[mf][2], af[mf][3], addr);
            }
#pragma unroll
            for (int g = 0; g < 4; g++) {
                uint32_t addr = bS + (uint32_t)(b_nl + g * 16) * ROWB
                              + (uint32_t)(((ks * 2 + b_ks) ^ fb) << 4);
                ldsm4(bf[g][0], bf[g][1], bf[g][2], bf[g][3], addr);
            }
#pragma unroll
            for (int mf = 0; mf < 4; mf++)
#pragma unroll
                for (int nf = 0; nf < 8; nf++)
                    mma16816(acc[mf][nf], af[mf], &bf[nf >> 1][(nf & 1) * 2]);
        }
        bufc = (bufc == 2) ? 0 : bufc + 1;
        bufs = (bufs == 2) ? 0 : bufs + 1;
    }

    // ---- epilogue ----
    const int gid = l >> 2, tg = l & 3;
    if (PHASE == 1) {
#pragma unroll
        for (int mf = 0; mf < 4; mf++) {
#pragma unroll
            for (int half = 0; half < 2; half++) {
                int row = warp_m + mf * 16 + gid + half * 8;
                int slot = e * CAP + m0 + row;
                __half* hrow = g_h16 + (size_t)slot * F_DIM;
#pragma unroll
                for (int nf = 0; nf < 8; nf++) {
                    int col = n0 + warp_n + nf * 8 + tg * 2;
                    float v0 = fmaxf(acc[mf][nf][half * 2 + 0], 0.f);
                    float v1 = fmaxf(acc[mf][nf][half * 2 + 1], 0.f);
                    *(__half2*)(hrow + col) = __halves2half2(__float2half_rn(v0), __float2half_rn(v1));
                }
            }
        }
    } else {
#pragma unroll
        for (int mf = 0; mf < 4; mf++) {
#pragma unroll
            for (int half = 0; half < 2; half++) {
                int row = warp_m + mf * 16 + gid + half * 8;
                int slot = e * CAP + m0 + row;
                int tok = g_tok_of_slot[slot];
                if (tok < 0) continue;
                float g = g_slot_gate[slot];
                float* orow = out + (size_t)tok * D_DIM;
#pragma unroll
                for (int nf = 0; nf < 8; nf++) {
                    int col = n0 + warp_n + nf * 8 + tg * 2;
                    float2 v;
                    v.x = acc[mf][nf][half * 2 + 0] * g;
                    v.y = acc[mf][nf][half * 2 + 1] * g;
                    *(float2*)(orow + col) = v;
                }
            }
        }
    }
}

// ---------------- launch ----------------
extern "C" void kernel_launch(void* const* d_in, const int* in_sizes, int n_in,
                              void* d_out, int out_size) {
    const float* x  = (const float*)d_in[0];
    const float* Wr = (const float*)d_in[1];
    const float* W1 = (const float*)d_in[2];
    const float* W2 = (const float*)d_in[3];
    float* out = (float*)d_out;

    // 0: mega setup — router | reset | convert W1 | convert W2 (one launch)
    mega_setup_kernel<<<2112 + 8192 + 8192, 256>>>(x, Wr, W1, W2);
    // 1: slot assignment (computes its own prefix bases) + output zeroing
    assign_kernel<<<64 + 2048, CHUNK>>>(out);
    // 2: GEMM1 (block 0 also re-zeroes chunk histogram for graph replay)
    moe_mma_gemm<1><<<dim3(F_DIM / BN, CAP / BM, E_NUM), NTHREADS>>>(nullptr);
    // 3: GEMM2
    moe_mma_gemm<2><<<dim3(D_DIM / BN, CAP / BM, E_NUM), NTHREADS>>>(out);
}

// round 17
// speedup vs baseline: 1.0473x; 1.0473x over previous
#include <cuda_runtime.h>
#include <cuda_fp16.h>
#include <cstdint>
#include <cstddef>

// Problem constants (B=8, S=2048, D=1024, F=4096, E=8, capacity_factor=1.0)
#define T_TOK   16384
#define D_DIM   1024
#define F_DIM   4096
#define E_NUM   8
#define CAP     2048
#define CHUNK   256
#define NCHUNK  (T_TOK / CHUNK)

#define BM 128
#define BN 128
#define NTHREADS 128
#define ROWB 64              // 32 fp16 per k-tile row
#define STAGE_B 16384        // A 8KB + B 8KB per stage (3 stages = 48KB)

// ---------------- device scratch (~288 MB, proven-safe) ----------------
__device__ int   g_eidx[T_TOK];
__device__ float g_gate[T_TOK];
__device__ int   g_counts[NCHUNK][E_NUM];     // zero-init; GEMM1 re-zeroes after assign reads
__device__ int   g_tok_of_slot[E_NUM * CAP];
__device__ float g_slot_gate[E_NUM * CAP];

__device__ __half g_x16[(size_t)T_TOK * D_DIM];               //  32 MB
__device__ __half g_wt[(size_t)E_NUM * F_DIM * D_DIM];        //  64 MB  W1t
__device__ __half g_wt2[(size_t)E_NUM * D_DIM * F_DIM];       //  64 MB  W2t
__device__ __half g_h16[(size_t)E_NUM * CAP * F_DIM];         // 128 MB  H
__device__ uint4  g_zrow[512];                                //   8 KB zero row

// ---------------- PTX helpers ----------------
__device__ __forceinline__ uint32_t smem_u32(const void* p) {
    uint32_t a;
    asm("{ .reg .u64 t; cvta.to.shared.u64 t, %1; cvt.u32.u64 %0, t; }" : "=r"(a) : "l"(p));
    return a;
}
__device__ __forceinline__ void sts128(uint32_t a, uint4 v) {
    asm volatile("st.shared.v4.b32 [%0], {%1,%2,%3,%4};"
                 :: "r"(a), "r"(v.x), "r"(v.y), "r"(v.z), "r"(v.w) : "memory");
}
__device__ __forceinline__ void ldsm4(uint32_t& r0, uint32_t& r1, uint32_t& r2, uint32_t& r3, uint32_t a) {
    asm volatile("ldmatrix.sync.aligned.m8n8.x4.shared.b16 {%0,%1,%2,%3}, [%4];"
                 : "=r"(r0), "=r"(r1), "=r"(r2), "=r"(r3) : "r"(a));
}
__device__ __forceinline__ void mma16816(float* c, const uint32_t* a, const uint32_t* b) {
    asm volatile("mma.sync.aligned.m16n8k16.row.col.f32.f16.f16.f32 "
                 "{%0,%1,%2,%3}, {%4,%5,%6,%7}, {%8,%9}, {%0,%1,%2,%3};"
                 : "+f"(c[0]), "+f"(c[1]), "+f"(c[2]), "+f"(c[3])
                 : "r"(a[0]), "r"(a[1]), "r"(a[2]), "r"(a[3]), "r"(b[0]), "r"(b[1]));
}

// ---------------- 64x64 transpose+convert body (uses caller smem) ----------
// src [e][K][N] f32 (N contiguous) -> dst [e][N][K] fp16
__device__ __forceinline__ void convert_w_tile64(const float* __restrict__ W,
                                                 __half* __restrict__ dstbuf,
                                                 float* sbuf,   // >= 64*65 floats
                                                 int K, int N, int e, int k0, int n0,
                                                 int tid) {
    const float* src = W + (size_t)e * K * N;
    __half* d = dstbuf + (size_t)e * N * K;
    const int tx = tid & 15, ty = tid >> 4;        // (16, 16)
#pragma unroll
    for (int i = 0; i < 4; i++) {
        int kl = ty + i * 16;
        float4 v = *(const float4*)(src + (size_t)(k0 + kl) * N + n0 + tx * 4);
        float* row = sbuf + kl * 65;
        row[tx * 4 + 0] = v.x;
        row[tx * 4 + 1] = v.y;
        row[tx * 4 + 2] = v.z;
        row[tx * 4 + 3] = v.w;
    }
    __syncthreads();
#pragma unroll
    for (int i = 0; i < 4; i++) {
        int nl = ty + i * 16;
        __half h[4];
#pragma unroll
        for (int j = 0; j < 4; j++)
            h[j] = __float2half_rn(sbuf[(tx * 4 + j) * 65 + nl]);
        *(uint2*)(d + (size_t)(n0 + nl) * K + k0 + tx * 4) = *(uint2*)h;
    }
}

// ------ mega setup: router | reset | convert W1 | convert W2 (ONE launch) --
__global__ void mega_setup_kernel(const float* __restrict__ x,
                                  const float* __restrict__ Wr,
                                  const float* __restrict__ W1,
                                  const float* __restrict__ W2) {
    __shared__ float sh[8192];                    // 32 KB shared: Wr cache / transpose tile
    const int b = blockIdx.x;
    const int tid = threadIdx.x;

    if (b < 2048) {
        // ---- router: 8 warps, one token per warp
        for (int i = tid; i < D_DIM * E_NUM; i += blockDim.x)
            sh[i] = Wr[i];
        __syncthreads();

        const int warp = tid >> 5;
        const int lane = tid & 31;
        const int tok  = b * 8 + warp;
        const float* xr = x + (size_t)tok * D_DIM;
        __half* xo = g_x16 + (size_t)tok * D_DIM;

        float acc[E_NUM];
#pragma unroll
        for (int e = 0; e < E_NUM; e++) acc[e] = 0.f;
        for (int d = lane; d < D_DIM; d += 32) {
            float xv = xr[d];
            xo[d] = __float2half_rn(xv);
            const float* w = &sh[d * E_NUM];
#pragma unroll
            for (int e = 0; e < E_NUM; e++) acc[e] += xv * w[e];
        }
#pragma unroll
        for (int e = 0; e < E_NUM; e++) {
#pragma unroll
            for (int o = 16; o > 0; o >>= 1)
                acc[e] += __shfl_xor_sync(0xffffffffu, acc[e], o);
        }
        if (lane == 0) {
            int best = 0; float bm = acc[0];
#pragma unroll
            for (int e = 1; e < E_NUM; e++)
                if (acc[e] > bm) { bm = acc[e]; best = e; }
            float s = 0.f;
#pragma unroll
            for (int e = 0; e < E_NUM; e++) s += __expf(acc[e] - bm);
            g_eidx[tok] = best;
            g_gate[tok] = 1.0f / s;
            atomicAdd(&g_counts[tok >> 8][best], 1);
        }
    } else if (b < 2112) {
        int i = (b - 2048) * 256 + tid;
        g_tok_of_slot[i] = -1;
        g_slot_gate[i]   = 0.f;
        if (i < 512) g_zrow[i] = make_uint4(0u, 0u, 0u, 0u);
    } else if (b < 2112 + 8192) {
        int idx = b - 2112;
        int kt = idx & 15;             // 1024/64 = 16
        int nt = (idx >> 4) & 63;      // 4096/64 = 64
        int e  = idx >> 10;
        convert_w_tile64(W1, g_wt, sh, D_DIM, F_DIM, e, kt * 64, nt * 64, tid);
    } else {
        int idx = b - (2112 + 8192);
        int kt = idx & 63;             // 4096/64 = 64
        int nt = (idx >> 6) & 15;      // 1024/64 = 16
        int e  = idx >> 10;
        convert_w_tile64(W2, g_wt2, sh, F_DIM, D_DIM, e, kt * 64, nt * 64, tid);
    }
}

// ---------------- assign (in-place prefix base + zero output) --------------
__global__ void assign_kernel(float* __restrict__ out) {
    if (blockIdx.x >= 64) {
        size_t off = (size_t)(blockIdx.x - 64) * 256 + threadIdx.x;
        float4 z = make_float4(0.f, 0.f, 0.f, 0.f);
        float4* o = (float4*)out;
#pragma unroll
        for (int j = 0; j < 8; j++)
            o[off + (size_t)j * 524288] = z;
        return;
    }
    __shared__ int se[CHUNK];
    __shared__ int sbase[E_NUM];
    const int c = blockIdx.x;
    const int tid = threadIdx.x;
    const int w = tid >> 5, lane = tid & 31;

    // warp w computes base[w] = sum over chunks j < c of counts[j][w]
    {
        int v = 0;
        if (lane < c)      v  = g_counts[lane][w];
        if (lane + 32 < c) v += g_counts[lane + 32][w];
#pragma unroll
        for (int o = 16; o > 0; o >>= 1)
            v += __shfl_xor_sync(0xffffffffu, v, o);
        if (lane == 0) sbase[w] = v;
    }

    int tok = c * CHUNK + tid;
    int e = g_eidx[tok];
    se[tid] = e;
    __syncthreads();
    int local = 0;
    for (int j = 0; j < tid; j++) local += (se[j] == e);
    int rank = sbase[e] + local;
    if (rank < CAP) {
        int slot = e * CAP + rank;
        g_tok_of_slot[slot] = tok;
        g_slot_gate[slot]   = g_gate[tok];
    }
}

// ---------------- HMMA GEMM (frozen core; PHASE 2 adds split-K=2) ----------
// smem swizzle: 16B granule g of row r stored at granule (g ^ ((r>>1)&3))
// PHASE 1: H = relu( gather(x16) @ W1t^T )  (K=1024); block 0 re-zeroes counts
// PHASE 2: out[tok] += gate * ( H @ W2t^T ) (K=4096, 2 CTAs split K, atomicAdd)
template <int PHASE>
__global__ void __launch_bounds__(NTHREADS, 2)
moe_mma_gemm(float* __restrict__ out) {
    constexpr int KSPL = (PHASE == 1) ? 1 : 2;
    constexpr int KA   = ((PHASE == 1) ? D_DIM : F_DIM) / KSPL;  // K per CTA
    constexpr int NC   = KA / 32;                                // 32 / 64 k-tiles
    constexpr int NT   = (PHASE == 1) ? F_DIM : D_DIM;
    constexpr int NBX  = NT / BN;                                // 32 / 8
    constexpr int KFULL = (PHASE == 1) ? D_DIM : F_DIM;

    __shared__ uint4 dsm[3072];                 // 48 KB: 3 stages x (A 8KB + B 8KB)
    const uint32_t sbase = smem_u32(dsm);

    const int tid = threadIdx.x;
    const int e  = blockIdx.z;
    const int m0 = blockIdx.y * BM;
    const int n0 = (blockIdx.x & (NBX - 1)) * BN;
    const int ks = blockIdx.x / NBX;            // 0 for PHASE 1; 0/1 for PHASE 2
    const size_t ksoff = (size_t)ks * KA * 2;   // byte offset into K range

    if (PHASE == 1 && blockIdx.x == 0 && blockIdx.y == 0 && blockIdx.z == 0) {
        // re-zero chunk histogram for next replay (stream-ordered after assign)
        int* cnt = &g_counts[0][0];
#pragma unroll
        for (int j = 0; j < 4; j++)
            cnt[tid + j * 128] = 0;
    }

    // ---- load mapping
    const int rbase = tid >> 2;
    const int cix   = tid & 3;
    const uint32_t dst0 = (uint32_t)rbase * ROWB + (uint32_t)((cix ^ ((rbase >> 1) & 3)) << 4);

    const char* pA[4];
    const char* pB[4];
    uint32_t    mskA = 0;
#pragma unroll
    for (int i = 0; i < 4; i++) {
        int row = rbase + i * 32;
        if (PHASE == 1) {
            int tok = g_tok_of_slot[e * CAP + m0 + row];
            if (tok >= 0) { pA[i] = (const char*)(g_x16 + (size_t)tok * D_DIM) + cix * 16; mskA |= (1u << i); }
            else          { pA[i] = (const char*)g_zrow; }
        } else {
            pA[i] = (const char*)(g_h16 + (size_t)(e * CAP + m0 + row) * F_DIM) + ksoff + cix * 16;
            mskA |= (1u << i);
        }
        const __half* wb = (PHASE == 1) ? g_wt : g_wt2;
        pB[i] = (const char*)(wb + ((size_t)e * NT + n0 + row) * KFULL) + ksoff + cix * 16;
    }

    uint4 rA[4], rB[4];
    auto ldg_tile = [&](int c) {
        uint32_t koff = (uint32_t)c * ROWB;
#pragma unroll
        for (int i = 0; i < 4; i++) {
            rA[i] = *(const uint4*)(pA[i] + (((mskA >> i) & 1) ? koff : 0u));
            rB[i] = *(const uint4*)(pB[i] + koff);
        }
    };
    auto sts_tile = [&](int buf) {
        uint32_t aS = sbase + (uint32_t)buf * STAGE_B;
        uint32_t bS = aS + 8192;
#pragma unroll
        for (int i = 0; i < 4; i++) {
            sts128(aS + dst0 + i * 2048, rA[i]);
            sts128(bS + dst0 + i * 2048, rB[i]);
        }
    };

    // ---- compute mapping: 4 warps 2x2, warp tile 64x64
    const int w = tid >> 5, l = tid & 31;
    const int warp_m = (w & 1) * 64, warp_n = (w >> 1) * 64;
    const int a_ml = warp_m + (l & 15);
    const int a_ks = (l >> 4);
    const int b_nl = warp_n + (l & 7) + ((l & 16) >> 1);
    const int b_ks = (l >> 3) & 1;
    const int fa = (a_ml >> 1) & 3, fb = (b_nl >> 1) & 3;

    float acc[4][8][4];
#pragma unroll
    for (int i = 0; i < 4; i++)
#pragma unroll
        for (int j = 0; j < 8; j++)
#pragma unroll
            for (int q = 0; q < 4; q++) acc[i][j][q] = 0.f;

    ldg_tile(0);
    sts_tile(0);
    ldg_tile(1);

    int bufc = 0, bufs = 1;
#pragma unroll 2
    for (int c = 0; c < NC; c++) {
        if (c + 1 < NC) sts_tile(bufs);
        if (c + 2 < NC) ldg_tile(c + 2);
        __syncthreads();

        uint32_t aS = sbase + (uint32_t)bufc * STAGE_B;
        uint32_t bS = aS + 8192;
#pragma unroll
        for (int ks2 = 0; ks2 < 2; ks2++) {
            uint32_t af[4][4], bf[4][4];
#pragma unroll
            for (int mf = 0; mf < 4; mf++) {
                uint32_t addr = aS + (uint32_t)(a_ml + mf * 16) * ROWB
                              + (uint32_t)(((ks2 * 2 + a_ks) ^ fa) << 4);
                ldsm4(af[mf][0], af[mf][1], af[mf][2], af[mf][3], addr);
            }
#pragma unroll
            for (int g = 0; g < 4; g++) {
                uint32_t addr = bS + (uint32_t)(b_nl + g * 16) * ROWB
                              + (uint32_t)(((ks2 * 2 + b_ks) ^ fb) << 4);
                ldsm4(bf[g][0], bf[g][1], bf[g][2], bf[g][3], addr);
            }
#pragma unroll
            for (int mf = 0; mf < 4; mf++)
#pragma unroll
                for (int nf = 0; nf < 8; nf++)
                    mma16816(acc[mf][nf], af[mf], &bf[nf >> 1][(nf & 1) * 2]);
        }
        bufc = (bufc == 2) ? 0 : bufc + 1;
        bufs = (bufs == 2) ? 0 : bufs + 1;
    }

    // ---- epilogue ----
    const int gid = l >> 2, tg = l & 3;
    if (PHASE == 1) {
#pragma unroll
        for (int mf = 0; mf < 4; mf++) {
#pragma unroll
            for (int half = 0; half < 2; half++) {
                int row = warp_m + mf * 16 + gid + half * 8;
                int slot = e * CAP + m0 + row;
                __half* hrow = g_h16 + (size_t)slot * F_DIM;
#pragma unroll
                for (int nf = 0; nf < 8; nf++) {
                    int col = n0 + warp_n + nf * 8 + tg * 2;
                    float v0 = fmaxf(acc[mf][nf][half * 2 + 0], 0.f);
                    float v1 = fmaxf(acc[mf][nf][half * 2 + 1], 0.f);
                    *(__half2*)(hrow + col) = __halves2half2(__float2half_rn(v0), __float2half_rn(v1));
                }
            }
        }
    } else {
        // split-K partials: atomicAdd onto pre-zeroed output (2 commutative
        // contributions -> bit-deterministic)
#pragma unroll
        for (int mf = 0; mf < 4; mf++) {
#pragma unroll
            for (int half = 0; half < 2; half++) {
                int row = warp_m + mf * 16 + gid + half * 8;
                int slot = e * CAP + m0 + row;
                int tok = g_tok_of_slot[slot];
                if (tok < 0) continue;
                float g = g_slot_gate[slot];
                float* orow = out + (size_t)tok * D_DIM;
#pragma unroll
                for (int nf = 0; nf < 8; nf++) {
                    int col = n0 + warp_n + nf * 8 + tg * 2;
                    atomicAdd(orow + col,     acc[mf][nf][half * 2 + 0] * g);
                    atomicAdd(orow + col + 1, acc[mf][nf][half * 2 + 1] * g);
                }
            }
        }
    }
}

// ---------------- launch ----------------
extern "C" void kernel_launch(void* const* d_in, const int* in_sizes, int n_in,
                              void* d_out, int out_size) {
    const float* x  = (const float*)d_in[0];
    const float* Wr = (const float*)d_in[1];
    const float* W1 = (const float*)d_in[2];
    const float* W2 = (const float*)d_in[3];
    float* out = (float*)d_out;

    // 0: mega setup — router | reset | convert W1 | convert W2 (one launch)
    mega_setup_kernel<<<2112 + 8192 + 8192, 256>>>(x, Wr, W1, W2);
    // 1: slot assignment (computes its own prefix bases) + output zeroing
    assign_kernel<<<64 + 2048, CHUNK>>>(out);
    // 2: GEMM1 (block 0 also re-zeroes chunk histogram for graph replay)
    moe_mma_gemm<1><<<dim3(F_DIM / BN, CAP / BM, E_NUM), NTHREADS>>>(nullptr);
    // 3: GEMM2 with split-K=2 (grid.x = 8 n-tiles x 2 k-splits)
    moe_mma_gemm<2><<<dim3((D_DIM / BN) * 2, CAP / BM, E_NUM), NTHREADS>>>(out);
}